// round 15
// baseline (speedup 1.0000x reference)
#include <cuda_runtime.h>
#include <cuda_bf16.h>
#include <math.h>
#include <stdint.h>

#define BB    2
#define SS    2048
#define NTOK  4096
#define DD    2048
#define EE    16
#define CAP   640
#define SLOTP 768
#define KK    2048
#define NCH2  96                  // K' = 3*2048 in chunks of 64 (32 groups x 3 terms)

typedef __nv_bfloat16 bf16;

// ---------------- scratch ----------------
__device__ bf16  g_Xh[(size_t)EE * SLOTP * KK];
__device__ bf16  g_Xl[(size_t)EE * SLOTP * KK];
__device__ bf16  g_Gh[(size_t)EE * KK * KK];
__device__ bf16  g_Gl[(size_t)EE * KK * KK];
__device__ bf16  g_Uh[(size_t)EE * KK * KK];
__device__ bf16  g_Ul[(size_t)EE * KK * KK];
__device__ bf16  g_Dh[(size_t)EE * KK * KK];
__device__ bf16  g_Dl[(size_t)EE * KK * KK];
__device__ bf16  g_Hh[(size_t)EE * SLOTP * KK];
__device__ bf16  g_Hl[(size_t)EE * SLOTP * KK];
__device__ float g_Y [(size_t)EE * SLOTP * KK];
__device__ int   g_top[NTOK * 2];
__device__ float g_w[NTOK * 2];
__device__ int   g_slot[NTOK * 2];
__device__ int   g_tok[EE * CAP];
__device__ int   g_cnt[EE];

static __device__ __forceinline__ float silu_f(float p) { return p / (1.0f + __expf(-p)); }

static __device__ __forceinline__ uint32_t smem_u32(const void* p) {
    uint32_t a;
    asm("{ .reg .u64 t; cvta.to.shared.u64 t, %1; cvt.u32.u64 %0, t; }" : "=r"(a) : "l"(p));
    return a;
}
#define CP16(dst, src) asm volatile("cp.async.cg.shared.global [%0], [%1], 16;" :: "r"(dst), "l"(src))
#define CP_COMMIT()    asm volatile("cp.async.commit_group;")
#define CP_WAIT0()     asm volatile("cp.async.wait_group 0;")

static __device__ __forceinline__ void ldsm4(uint32_t* r, uint32_t a) {
    asm volatile("ldmatrix.sync.aligned.m8n8.x4.shared.b16 {%0,%1,%2,%3}, [%4];"
                 : "=r"(r[0]), "=r"(r[1]), "=r"(r[2]), "=r"(r[3]) : "r"(a));
}
static __device__ __forceinline__ void mma_bf16(float* c, const uint32_t* a, uint32_t b0, uint32_t b1) {
    asm volatile("mma.sync.aligned.m16n8k16.row.col.f32.bf16.bf16.f32 "
                 "{%0,%1,%2,%3}, {%4,%5,%6,%7}, {%8,%9}, {%0,%1,%2,%3};"
                 : "+f"(c[0]), "+f"(c[1]), "+f"(c[2]), "+f"(c[3])
                 : "r"(a[0]), "r"(a[1]), "r"(a[2]), "r"(a[3]), "r"(b0), "r"(b1));
}
static __device__ __forceinline__ void split2(float x, uint16_t& h, uint16_t& l) {
    bf16 hb = __float2bfloat16_rn(x);
    bf16 lb = __float2bfloat16_rn(x - __bfloat162float(hb));
    h = __bfloat16_as_ushort(hb);
    l = __bfloat16_as_ushort(lb);
}
static __device__ __forceinline__ void split4_packed(float4 v, uint2& ho, uint2& lo) {
    __nv_bfloat162 h01 = __floats2bfloat162_rn(v.x, v.y);
    __nv_bfloat162 h23 = __floats2bfloat162_rn(v.z, v.w);
    float rx = v.x - __low2float(h01), ry = v.y - __high2float(h01);
    float rz = v.z - __low2float(h23), rw = v.w - __high2float(h23);
    __nv_bfloat162 l01 = __floats2bfloat162_rn(rx, ry);
    __nv_bfloat162 l23 = __floats2bfloat162_rn(rz, rw);
    ho.x = *reinterpret_cast<uint32_t*>(&h01); ho.y = *reinterpret_cast<uint32_t*>(&h23);
    lo.x = *reinterpret_cast<uint32_t*>(&l01); lo.y = *reinterpret_cast<uint32_t*>(&l23);
}

// ---------------- router ----------------
__global__ void router_kernel(const float* __restrict__ hs, const float* __restrict__ wg) {
    int n = blockIdx.x, b = n & 1, s = n >> 1;
    const float* tok = hs + (size_t)b * SS * DD + (size_t)s * DD;
    float acc[EE];
#pragma unroll
    for (int e = 0; e < EE; e++) acc[e] = 0.0f;
    for (int d = threadIdx.x; d < DD; d += 128) {
        float x = tok[d];
#pragma unroll
        for (int e = 0; e < EE; e++) acc[e] += x * wg[e * DD + d];
    }
#pragma unroll
    for (int e = 0; e < EE; e++)
#pragma unroll
        for (int off = 16; off > 0; off >>= 1)
            acc[e] += __shfl_xor_sync(0xffffffffu, acc[e], off);
    __shared__ float red[4][EE];
    int warp = threadIdx.x >> 5, lane = threadIdx.x & 31;
    if (lane == 0)
#pragma unroll
        for (int e = 0; e < EE; e++) red[warp][e] = acc[e];
    __syncthreads();
    if (threadIdx.x == 0) {
        float g[EE];
#pragma unroll
        for (int e = 0; e < EE; e++) g[e] = red[0][e] + red[1][e] + red[2][e] + red[3][e];
        float mx = g[0];
#pragma unroll
        for (int e = 1; e < EE; e++) mx = fmaxf(mx, g[e]);
        float sum = 0.0f;
#pragma unroll
        for (int e = 0; e < EE; e++) { g[e] = __expf(g[e] - mx); sum += g[e]; }
        float inv = 1.0f / sum;
#pragma unroll
        for (int e = 0; e < EE; e++) g[e] *= inv;
        int e1 = 0; float v1 = g[0];
#pragma unroll
        for (int e = 1; e < EE; e++) if (g[e] > v1) { v1 = g[e]; e1 = e; }
        int e2 = -1; float v2 = -1.0f;
#pragma unroll
        for (int e = 0; e < EE; e++) if (e != e1 && g[e] > v2) { v2 = g[e]; e2 = e; }
        float denom = v1 + v2;
        const float EPS = 1.1920929e-07f;
        if (denom < EPS) denom = EPS;
        g_top[2 * n] = e1; g_top[2 * n + 1] = e2;
        g_w[2 * n] = v1 / denom; g_w[2 * n + 1] = v2 / denom;
    }
}

// ---------------- assign ----------------
__global__ void assign_kernel() {
    int e = blockIdx.x;
    __shared__ int warpsum[8];
    __shared__ int s_running;
    if (threadIdx.x == 0) s_running = 0;
    __syncthreads();
    int lane = threadIdx.x & 31, warp = threadIdx.x >> 5;
    for (int k = 0; k < 2; k++)
        for (int c0 = 0; c0 < NTOK; c0 += 256) {
            int n = c0 + threadIdx.x;
            int f = (g_top[2 * n + k] == e) ? 1 : 0;
            unsigned bal = __ballot_sync(0xffffffffu, f);
            int lpre = __popc(bal & ((1u << lane) - 1u));
            if (lane == 0) warpsum[warp] = __popc(bal);
            __syncthreads();
            int wpre = 0, tot = 0;
#pragma unroll
            for (int w = 0; w < 8; w++) { int v = warpsum[w]; if (w < warp) wpre += v; tot += v; }
            int pos = s_running + wpre + lpre;
            if (f) {
                if (pos < CAP) { g_slot[2 * n + k] = e * SLOTP + pos; g_tok[e * CAP + pos] = n; }
                else           { g_slot[2 * n + k] = -1; }
            }
            __syncthreads();
            if (threadIdx.x == 0) s_running += tot;
            __syncthreads();
        }
    if (threadIdx.x == 0) g_cnt[e] = (s_running < CAP) ? s_running : CAP;
}

// ---------------- prep_w: MLP=4 (at DRAM floor) ----------------
__global__ void prep_w_kernel(const float* __restrict__ gp, const float* __restrict__ up,
                              const float* __restrict__ dp,
                              bf16* __restrict__ Gh, bf16* __restrict__ Gl,
                              bf16* __restrict__ Uh, bf16* __restrict__ Ul,
                              bf16* __restrict__ Dh, bf16* __restrict__ Dl) {
    const float* src = (blockIdx.y == 0) ? gp : (blockIdx.y == 1) ? up : dp;
    bf16* dh = (blockIdx.y == 0) ? Gh : (blockIdx.y == 1) ? Uh : Dh;
    bf16* dl = (blockIdx.y == 0) ? Gl : (blockIdx.y == 1) ? Ul : Dl;
    size_t blockbase = (size_t)blockIdx.x * 1024;     // in float4 units
    float4 v[4];
#pragma unroll
    for (int i = 0; i < 4; i++)
        v[i] = *(const float4*)(src + (blockbase + i * 256 + threadIdx.x) * 4);
    uint2 ho[4], lo[4];
#pragma unroll
    for (int i = 0; i < 4; i++) split4_packed(v[i], ho[i], lo[i]);
#pragma unroll
    for (int i = 0; i < 4; i++) {
        size_t idx = (blockbase + i * 256 + threadIdx.x) * 4;
        *(uint2*)(dh + idx) = ho[i];
        *(uint2*)(dl + idx) = lo[i];
    }
}

// ---------------- prep_x ----------------
__global__ void prep_x_kernel(const float* __restrict__ hs) {
    int e = blockIdx.y, p = blockIdx.x;
    int count = g_cnt[e];
    size_t row = (size_t)(e * SLOTP + p) * KK;
    if (p >= count) {
        for (int j = threadIdx.x; j < KK / 4; j += 256) {
            *(uint2*)(g_Xh + row + j * 4) = make_uint2(0, 0);
            *(uint2*)(g_Xl + row + j * 4) = make_uint2(0, 0);
        }
        return;
    }
    int t = g_tok[e * CAP + p];
    const float* src = hs + ((size_t)(t & 1) * SS + (size_t)(t >> 1)) * DD;
    for (int j = threadIdx.x; j < KK / 4; j += 256) {
        float4 v = *(const float4*)(src + j * 4);
        uint2 ho, lo;
        split4_packed(v, ho, lo);
        *(uint2*)(g_Xh + row + j * 4) = ho;
        *(uint2*)(g_Xl + row + j * 4) = lo;
    }
}

// ---------------- GEMM geometry: BM=128, separate A/B rings of 3 slots -------
// Term order per k-group: (Ah*Bh), (Al*Bh), (Ah*Bl).
#define ROWB  144
#define TSZ   (128 * ROWB)        // 18432 per slot
#define BOFF  (3 * TSZ)           // B ring at 55296
#define GSMEM (6 * TSZ)           // 110592 -> 2 CTAs/SM

static __device__ __forceinline__ int slotA_of(int k, int j) { return (2 * k + (j == 1 ? 1 : 0)) % 3; }
static __device__ __forceinline__ int slotB_of(int k, int j) { return (2 * k + (j == 2 ? 1 : 0)) % 3; }

// ---------------- ffn1 fused: dual BN=64, SwiGLU epilogue ----------------
__global__ void __launch_bounds__(256, 2)
ffn1_kernel(const bf16* __restrict__ Ah, const bf16* __restrict__ Al,
            const bf16* __restrict__ Gh, const bf16* __restrict__ Gl,
            const bf16* __restrict__ Uh, const bf16* __restrict__ Ul) {
    int e = blockIdx.z;
    int count = g_cnt[e];
    int m0 = blockIdx.y * 128;
    if (m0 >= count) return;
    int n0 = blockIdx.x * 64;

    extern __shared__ char smem[];
    uint32_t sb = smem_u32(smem);
    int tid = threadIdx.x, lane = tid & 31, w = tid >> 5;
    int wm = w >> 1, wn = w & 1;

    const bf16* A_h = Ah + ((size_t)e * SLOTP + m0) * KK;
    const bf16* A_l = Al + ((size_t)e * SLOTP + m0) * KK;
    const bf16* G_h = Gh + (size_t)e * KK * KK + (size_t)n0 * KK;
    const bf16* G_l = Gl + (size_t)e * KK * KK + (size_t)n0 * KK;
    const bf16* U_h = Uh + (size_t)e * KK * KK + (size_t)n0 * KK;
    const bf16* U_l = Ul + (size_t)e * KK * KK + (size_t)n0 * KK;

    uint32_t aBase[2];
#pragma unroll
    for (int mt = 0; mt < 2; mt++)
        aBase[mt] = (uint32_t)((wm * 32 + mt * 16 + (lane & 15)) * ROWB + ((lane >> 4) << 4));
    uint32_t bBase[2][2];
    {
        int grp = lane >> 3, wi = lane & 7;
#pragma unroll
        for (int o = 0; o < 2; o++)
#pragma unroll
            for (int p = 0; p < 2; p++)
                bBase[o][p] = (uint32_t)((o * 64 + wn * 32 + p * 16 + ((grp >> 1) << 3) + wi) * ROWB
                                         + ((grp & 1) << 4));
    }

    float accP[2][4][4], accQ[2][4][4];
#pragma unroll
    for (int i = 0; i < 2; i++)
#pragma unroll
        for (int j = 0; j < 4; j++)
#pragma unroll
            for (int q = 0; q < 4; q++) { accP[i][j][q] = 0.0f; accQ[i][j][q] = 0.0f; }

    auto loadAB = [&](int c) {
        int k = c / 3, j = c - 3 * k;
        int k0 = k << 6;
        if (j != 2) {
            const bf16* As = (j == 1) ? A_l : A_h;
            uint32_t stb = sb + (uint32_t)slotA_of(k, j) * TSZ;
#pragma unroll
            for (int i = 0; i < 4; i++) {
                int id = tid + i * 256;
                int row = id >> 3, sub = id & 7;
                CP16(stb + row * ROWB + sub * 16, As + (size_t)row * KK + k0 + sub * 8);
            }
        }
        if (j != 1) {
            const bf16* Gs = (j == 2) ? G_l : G_h;
            const bf16* Us = (j == 2) ? U_l : U_h;
            uint32_t stb = sb + BOFF + (uint32_t)slotB_of(k, j) * TSZ;
#pragma unroll
            for (int i = 0; i < 4; i++) {
                int id = tid + i * 256;
                int row = id >> 3, sub = id & 7;
                const bf16* src = (row < 64) ? (Gs + (size_t)row * KK) : (Us + (size_t)(row - 64) * KK);
                CP16(stb + row * ROWB + sub * 16, src + k0 + sub * 8);
            }
        }
        CP_COMMIT();
    };

    loadAB(0);

    for (int c = 0; c < NCH2; c++) {
        CP_WAIT0();
        __syncthreads();
        if (c + 1 < NCH2) loadAB(c + 1);
        int k = c / 3, j = c - 3 * k;
        uint32_t baseA = sb + (uint32_t)slotA_of(k, j) * TSZ;
        uint32_t baseB = sb + BOFF + (uint32_t)slotB_of(k, j) * TSZ;
#pragma unroll
        for (int ks = 0; ks < 4; ks++) {
            uint32_t off = (uint32_t)(ks * 32);
            uint32_t a[2][4], bg[2][4], bu[2][4];
            ldsm4(a[0], baseA + aBase[0] + off);
            ldsm4(a[1], baseA + aBase[1] + off);
#pragma unroll
            for (int p = 0; p < 2; p++) { ldsm4(bg[p], baseB + bBase[0][p] + off);
                                          ldsm4(bu[p], baseB + bBase[1][p] + off); }
#pragma unroll
            for (int mt = 0; mt < 2; mt++)
#pragma unroll
                for (int p = 0; p < 2; p++) {
                    mma_bf16(accP[mt][2 * p],     a[mt], bg[p][0], bg[p][1]);
                    mma_bf16(accP[mt][2 * p + 1], a[mt], bg[p][2], bg[p][3]);
                    mma_bf16(accQ[mt][2 * p],     a[mt], bu[p][0], bu[p][1]);
                    mma_bf16(accQ[mt][2 * p + 1], a[mt], bu[p][2], bu[p][3]);
                }
        }
    }

    // epilogue: SwiGLU + split -> Hh/Hl
    size_t rowbase = (size_t)e * SLOTP + m0;
#pragma unroll
    for (int mt = 0; mt < 2; mt++) {
        int row = wm * 32 + mt * 16 + (lane >> 2);
#pragma unroll
        for (int half = 0; half < 2; half++) {
            int rr = row + half * 8;
            bf16* Hhp = g_Hh + (rowbase + rr) * KK + n0;
            bf16* Hlp = g_Hl + (rowbase + rr) * KK + n0;
#pragma unroll
            for (int nt = 0; nt < 4; nt++) {
                int col = wn * 32 + nt * 8 + ((lane & 3) << 1);
                float p0 = accP[mt][nt][2 * half],     q0 = accQ[mt][nt][2 * half];
                float p1 = accP[mt][nt][2 * half + 1], q1 = accQ[mt][nt][2 * half + 1];
                float h0 = silu_f(p0) * q0, h1 = silu_f(p1) * q1;
                uint16_t hh0, ll0, hh1, ll1;
                split2(h0, hh0, ll0); split2(h1, hh1, ll1);
                *(uint32_t*)(Hhp + col) = (uint32_t)hh0 | ((uint32_t)hh1 << 16);
                *(uint32_t*)(Hlp + col) = (uint32_t)ll0 | ((uint32_t)ll1 << 16);
            }
        }
    }
}

// ---------------- ffn2: Y = H dp^T (BM=128, BN=128, 256 thr) ----------------
__global__ void __launch_bounds__(256, 2)
ffn2_kernel(const bf16* __restrict__ Ah, const bf16* __restrict__ Al,
            const bf16* __restrict__ Bh, const bf16* __restrict__ Bl,
            float* __restrict__ C) {
    int e = blockIdx.z;
    int count = g_cnt[e];
    int m0 = blockIdx.y * 128;
    if (m0 >= count) return;
    int n0 = blockIdx.x * 128;

    extern __shared__ char smem[];
    uint32_t sb = smem_u32(smem);
    int tid = threadIdx.x, lane = tid & 31, w = tid >> 5;
    int wm = w >> 1, wn = w & 1;

    const bf16* A_h = Ah + ((size_t)e * SLOTP + m0) * KK;
    const bf16* A_l = Al + ((size_t)e * SLOTP + m0) * KK;
    const bf16* B_h = Bh + (size_t)e * KK * KK + (size_t)n0 * KK;
    const bf16* B_l = Bl + (size_t)e * KK * KK + (size_t)n0 * KK;

    uint32_t aBase[2];
#pragma unroll
    for (int mt = 0; mt < 2; mt++)
        aBase[mt] = (uint32_t)((wm * 32 + mt * 16 + (lane & 15)) * ROWB + ((lane >> 4) << 4));
    uint32_t bBase[4];
    {
        int grp = lane >> 3, wi = lane & 7;
#pragma unroll
        for (int p = 0; p < 4; p++)
            bBase[p] = (uint32_t)((wn * 64 + p * 16 + ((grp >> 1) << 3) + wi) * ROWB + ((grp & 1) << 4));
    }

    float acc[2][8][4];
#pragma unroll
    for (int i = 0; i < 2; i++)
#pragma unroll
        for (int j = 0; j < 8; j++)
#pragma unroll
            for (int q = 0; q < 4; q++) acc[i][j][q] = 0.0f;

    auto loadAB = [&](int c) {
        int k = c / 3, j = c - 3 * k;
        int k0 = k << 6;
        if (j != 2) {
            const bf16* As = (j == 1) ? A_l : A_h;
            uint32_t stb = sb + (uint32_t)slotA_of(k, j) * TSZ;
#pragma unroll
            for (int i = 0; i < 4; i++) {
                int id = tid + i * 256;
                int row = id >> 3, sub = id & 7;
                CP16(stb + row * ROWB + sub * 16, As + (size_t)row * KK + k0 + sub * 8);
            }
        }
        if (j != 1) {
            const bf16* Bs = (j == 2) ? B_l : B_h;
            uint32_t stb = sb + BOFF + (uint32_t)slotB_of(k, j) * TSZ;
#pragma unroll
            for (int i = 0; i < 4; i++) {
                int id = tid + i * 256;
                int row = id >> 3, sub = id & 7;
                CP16(stb + row * ROWB + sub * 16, Bs + (size_t)row * KK + k0 + sub * 8);
            }
        }
        CP_COMMIT();
    };

    loadAB(0);

    for (int c = 0; c < NCH2; c++) {
        CP_WAIT0();
        __syncthreads();
        if (c + 1 < NCH2) loadAB(c + 1);
        int k = c / 3, j = c - 3 * k;
        uint32_t baseA = sb + (uint32_t)slotA_of(k, j) * TSZ;
        uint32_t baseB = sb + BOFF + (uint32_t)slotB_of(k, j) * TSZ;
#pragma unroll
        for (int ks = 0; ks < 4; ks++) {
            uint32_t off = (uint32_t)(ks * 32);
            uint32_t a[2][4], b[4][4];
            ldsm4(a[0], baseA + aBase[0] + off);
            ldsm4(a[1], baseA + aBase[1] + off);
#pragma unroll
            for (int p = 0; p < 4; p++) ldsm4(b[p], baseB + bBase[p] + off);
#pragma unroll
            for (int mt = 0; mt < 2; mt++)
#pragma unroll
                for (int p = 0; p < 4; p++) {
                    mma_bf16(acc[mt][2 * p],     a[mt], b[p][0], b[p][1]);
                    mma_bf16(acc[mt][2 * p + 1], a[mt], b[p][2], b[p][3]);
                }
        }
    }

    float* Cb = C + ((size_t)e * SLOTP + m0) * KK + n0;
#pragma unroll
    for (int mt = 0; mt < 2; mt++) {
        int row = wm * 32 + mt * 16 + (lane >> 2);
#pragma unroll
        for (int nt = 0; nt < 8; nt++) {
            int col = wn * 64 + nt * 8 + ((lane & 3) << 1);
            *(float2*)(Cb + (size_t)row * KK + col)       = make_float2(acc[mt][nt][0], acc[mt][nt][1]);
            *(float2*)(Cb + (size_t)(row + 8) * KK + col) = make_float2(acc[mt][nt][2], acc[mt][nt][3]);
        }
    }
}

// ---------------- combine ----------------
__global__ void combine_kernel(float* __restrict__ out) {
    int n = blockIdx.x;
    int s0 = g_slot[2 * n], s1 = g_slot[2 * n + 1];
    float w0 = g_w[2 * n], w1 = g_w[2 * n + 1];
    int b = n & 1, s = n >> 1;
    float* o = out + (size_t)b * SS * DD + (size_t)s * DD;
    const float* y0 = (s0 >= 0) ? (g_Y + (size_t)s0 * KK) : 0;
    const float* y1 = (s1 >= 0) ? (g_Y + (size_t)s1 * KK) : 0;
    for (int d4 = threadIdx.x; d4 < DD / 4; d4 += 256) {
        float4 v = make_float4(0.f, 0.f, 0.f, 0.f);
        if (y0) {
            float4 a = *(const float4*)(y0 + d4 * 4);
            v.x += w0 * a.x; v.y += w0 * a.y; v.z += w0 * a.z; v.w += w0 * a.w;
        }
        if (y1) {
            float4 a = *(const float4*)(y1 + d4 * 4);
            v.x += w1 * a.x; v.y += w1 * a.y; v.z += w1 * a.z; v.w += w1 * a.w;
        }
        *(float4*)(o + d4 * 4) = v;
    }
}

// ---------------- launch: fork prep_w onto a side stream ----------------
extern "C" void kernel_launch(void* const* d_in, const int* in_sizes, int n_in,
                              void* d_out, int out_size) {
    (void)in_sizes; (void)n_in; (void)out_size;
    const float* hs = (const float*)d_in[0];
    const float* wg = (const float*)d_in[1];
    const float* gp = (const float*)d_in[2];
    const float* up = (const float*)d_in[3];
    const float* dp = (const float*)d_in[4];
    float* out = (float*)d_out;

    static int inited = 0;
    static cudaStream_t s2;
    static cudaEvent_t ev_fork, ev_join;
    if (!inited) {
        cudaFuncSetAttribute(ffn1_kernel, cudaFuncAttributeMaxDynamicSharedMemorySize, GSMEM);
        cudaFuncSetAttribute(ffn2_kernel, cudaFuncAttributeMaxDynamicSharedMemorySize, GSMEM);
        cudaStreamCreateWithFlags(&s2, cudaStreamNonBlocking);
        cudaEventCreateWithFlags(&ev_fork, cudaEventDisableTiming);
        cudaEventCreateWithFlags(&ev_join, cudaEventDisableTiming);
        inited = 1;
    }

    bf16 *Gh, *Gl, *Uh, *Ul, *Dh, *Dl, *Xh, *Xl, *Hh, *Hl;
    float *Y;
    cudaGetSymbolAddress((void**)&Gh, g_Gh); cudaGetSymbolAddress((void**)&Gl, g_Gl);
    cudaGetSymbolAddress((void**)&Uh, g_Uh); cudaGetSymbolAddress((void**)&Ul, g_Ul);
    cudaGetSymbolAddress((void**)&Dh, g_Dh); cudaGetSymbolAddress((void**)&Dl, g_Dl);
    cudaGetSymbolAddress((void**)&Xh, g_Xh); cudaGetSymbolAddress((void**)&Xl, g_Xl);
    cudaGetSymbolAddress((void**)&Hh, g_Hh); cudaGetSymbolAddress((void**)&Hl, g_Hl);
    cudaGetSymbolAddress((void**)&Y, g_Y);

    // Fork: prep_w (independent, ~224us DRAM-bound) runs on s2 concurrently
    // with router/assign/prep_x (~90us) on the main stream.
    cudaEventRecord(ev_fork, 0);
    cudaStreamWaitEvent(s2, ev_fork, 0);
    prep_w_kernel<<<dim3(16384, 3), 256, 0, s2>>>(gp, up, dp, Gh, Gl, Uh, Ul, Dh, Dl);
    cudaEventRecord(ev_join, s2);

    router_kernel<<<NTOK, 128>>>(hs, wg);
    assign_kernel<<<EE, 256>>>();
    prep_x_kernel<<<dim3(SLOTP, EE), 256>>>(hs);

    // Join before the GEMMs consume the split weights.
    cudaStreamWaitEvent(0, ev_join, 0);

    ffn1_kernel<<<dim3(KK / 64, SLOTP / 128, EE), 256, GSMEM>>>(Xh, Xl, Gh, Gl, Uh, Ul);
    ffn2_kernel<<<dim3(KK / 128, SLOTP / 128, EE), 256, GSMEM>>>(Hh, Hl, Dh, Dl, Y);
    combine_kernel<<<NTOK, 256>>>(out);
}

// round 17
// speedup vs baseline: 1.4624x; 1.4624x over previous
#include <cuda_runtime.h>
#include <cuda_bf16.h>
#include <math.h>
#include <stdint.h>

#define BB    2
#define SS    2048
#define NTOK  4096
#define DD    2048
#define EE    16
#define CAP   640
#define SLOTP 768
#define KK    2048
#define NCH2  96                  // K' = 3*2048 in chunks of 64 (32 groups x 3 terms)

typedef __nv_bfloat16 bf16;

// ---------------- scratch ----------------
__device__ bf16  g_Xh[(size_t)EE * SLOTP * KK];
__device__ bf16  g_Xl[(size_t)EE * SLOTP * KK];
__device__ bf16  g_Gh[(size_t)EE * KK * KK];
__device__ bf16  g_Gl[(size_t)EE * KK * KK];
__device__ bf16  g_Uh[(size_t)EE * KK * KK];
__device__ bf16  g_Ul[(size_t)EE * KK * KK];
__device__ bf16  g_Dh[(size_t)EE * KK * KK];
__device__ bf16  g_Dl[(size_t)EE * KK * KK];
__device__ bf16  g_Hh[(size_t)EE * SLOTP * KK];
__device__ bf16  g_Hl[(size_t)EE * SLOTP * KK];
__device__ float g_Y [(size_t)EE * SLOTP * KK];
__device__ int   g_top[NTOK * 2];
__device__ float g_w[NTOK * 2];
__device__ int   g_slot[NTOK * 2];
__device__ int   g_tok[EE * CAP];
__device__ int   g_cnt[EE];

static __device__ __forceinline__ float silu_f(float p) { return p / (1.0f + __expf(-p)); }

static __device__ __forceinline__ uint32_t smem_u32(const void* p) {
    uint32_t a;
    asm("{ .reg .u64 t; cvta.to.shared.u64 t, %1; cvt.u32.u64 %0, t; }" : "=r"(a) : "l"(p));
    return a;
}
#define CP16(dst, src) asm volatile("cp.async.cg.shared.global [%0], [%1], 16;" :: "r"(dst), "l"(src))
#define CP_COMMIT()    asm volatile("cp.async.commit_group;")
#define CP_WAIT0()     asm volatile("cp.async.wait_group 0;")

static __device__ __forceinline__ void ldsm4(uint32_t* r, uint32_t a) {
    asm volatile("ldmatrix.sync.aligned.m8n8.x4.shared.b16 {%0,%1,%2,%3}, [%4];"
                 : "=r"(r[0]), "=r"(r[1]), "=r"(r[2]), "=r"(r[3]) : "r"(a));
}
static __device__ __forceinline__ void mma_bf16(float* c, const uint32_t* a, uint32_t b0, uint32_t b1) {
    asm volatile("mma.sync.aligned.m16n8k16.row.col.f32.bf16.bf16.f32 "
                 "{%0,%1,%2,%3}, {%4,%5,%6,%7}, {%8,%9}, {%0,%1,%2,%3};"
                 : "+f"(c[0]), "+f"(c[1]), "+f"(c[2]), "+f"(c[3])
                 : "r"(a[0]), "r"(a[1]), "r"(a[2]), "r"(a[3]), "r"(b0), "r"(b1));
}
static __device__ __forceinline__ void split2(float x, uint16_t& h, uint16_t& l) {
    bf16 hb = __float2bfloat16_rn(x);
    bf16 lb = __float2bfloat16_rn(x - __bfloat162float(hb));
    h = __bfloat16_as_ushort(hb);
    l = __bfloat16_as_ushort(lb);
}
static __device__ __forceinline__ void split4_packed(float4 v, uint2& ho, uint2& lo) {
    __nv_bfloat162 h01 = __floats2bfloat162_rn(v.x, v.y);
    __nv_bfloat162 h23 = __floats2bfloat162_rn(v.z, v.w);
    float rx = v.x - __low2float(h01), ry = v.y - __high2float(h01);
    float rz = v.z - __low2float(h23), rw = v.w - __high2float(h23);
    __nv_bfloat162 l01 = __floats2bfloat162_rn(rx, ry);
    __nv_bfloat162 l23 = __floats2bfloat162_rn(rz, rw);
    ho.x = *reinterpret_cast<uint32_t*>(&h01); ho.y = *reinterpret_cast<uint32_t*>(&h23);
    lo.x = *reinterpret_cast<uint32_t*>(&l01); lo.y = *reinterpret_cast<uint32_t*>(&l23);
}

// ---------------- router: 2 tokens per block, shared wg loads ----------------
__global__ void router_kernel(const float* __restrict__ hs, const float* __restrict__ wg) {
    int n0tok = blockIdx.x * 2;               // tokens n0tok, n0tok+1
    int b0 = n0tok & 1, s0 = n0tok >> 1;
    int n1tok = n0tok + 1;
    int b1 = n1tok & 1, s1 = n1tok >> 1;
    const float* tok0 = hs + (size_t)b0 * SS * DD + (size_t)s0 * DD;
    const float* tok1 = hs + (size_t)b1 * SS * DD + (size_t)s1 * DD;

    float acc0[EE], acc1[EE];
#pragma unroll
    for (int e = 0; e < EE; e++) { acc0[e] = 0.0f; acc1[e] = 0.0f; }
    for (int d = threadIdx.x; d < DD; d += 128) {
        float x0 = tok0[d];
        float x1 = tok1[d];
#pragma unroll
        for (int e = 0; e < EE; e++) {
            float wv = wg[e * DD + d];
            acc0[e] += x0 * wv;
            acc1[e] += x1 * wv;
        }
    }
#pragma unroll
    for (int e = 0; e < EE; e++) {
#pragma unroll
        for (int off = 16; off > 0; off >>= 1) {
            acc0[e] += __shfl_xor_sync(0xffffffffu, acc0[e], off);
            acc1[e] += __shfl_xor_sync(0xffffffffu, acc1[e], off);
        }
    }
    __shared__ float red[2][4][EE];
    int warp = threadIdx.x >> 5, lane = threadIdx.x & 31;
    if (lane == 0) {
#pragma unroll
        for (int e = 0; e < EE; e++) { red[0][warp][e] = acc0[e]; red[1][warp][e] = acc1[e]; }
    }
    __syncthreads();
    // threads 0 and 1 finalize token 0 / token 1 respectively
    if (threadIdx.x < 2) {
        int t = threadIdx.x;
        int n = n0tok + t;
        float g[EE];
#pragma unroll
        for (int e = 0; e < EE; e++)
            g[e] = red[t][0][e] + red[t][1][e] + red[t][2][e] + red[t][3][e];
        float mx = g[0];
#pragma unroll
        for (int e = 1; e < EE; e++) mx = fmaxf(mx, g[e]);
        float sum = 0.0f;
#pragma unroll
        for (int e = 0; e < EE; e++) { g[e] = __expf(g[e] - mx); sum += g[e]; }
        float inv = 1.0f / sum;
#pragma unroll
        for (int e = 0; e < EE; e++) g[e] *= inv;
        int e1 = 0; float v1 = g[0];
#pragma unroll
        for (int e = 1; e < EE; e++) if (g[e] > v1) { v1 = g[e]; e1 = e; }
        int e2 = -1; float v2 = -1.0f;
#pragma unroll
        for (int e = 0; e < EE; e++) if (e != e1 && g[e] > v2) { v2 = g[e]; e2 = e; }
        float denom = v1 + v2;
        const float EPS = 1.1920929e-07f;
        if (denom < EPS) denom = EPS;
        g_top[2 * n] = e1; g_top[2 * n + 1] = e2;
        g_w[2 * n] = v1 / denom; g_w[2 * n + 1] = v2 / denom;
    }
}

// ---------------- assign ----------------
__global__ void assign_kernel() {
    int e = blockIdx.x;
    __shared__ int warpsum[8];
    __shared__ int s_running;
    if (threadIdx.x == 0) s_running = 0;
    __syncthreads();
    int lane = threadIdx.x & 31, warp = threadIdx.x >> 5;
    for (int k = 0; k < 2; k++)
        for (int c0 = 0; c0 < NTOK; c0 += 256) {
            int n = c0 + threadIdx.x;
            int f = (g_top[2 * n + k] == e) ? 1 : 0;
            unsigned bal = __ballot_sync(0xffffffffu, f);
            int lpre = __popc(bal & ((1u << lane) - 1u));
            if (lane == 0) warpsum[warp] = __popc(bal);
            __syncthreads();
            int wpre = 0, tot = 0;
#pragma unroll
            for (int w = 0; w < 8; w++) { int v = warpsum[w]; if (w < warp) wpre += v; tot += v; }
            int pos = s_running + wpre + lpre;
            if (f) {
                if (pos < CAP) { g_slot[2 * n + k] = e * SLOTP + pos; g_tok[e * CAP + pos] = n; }
                else           { g_slot[2 * n + k] = -1; }
            }
            __syncthreads();
            if (threadIdx.x == 0) s_running += tot;
            __syncthreads();
        }
    if (threadIdx.x == 0) g_cnt[e] = (s_running < CAP) ? s_running : CAP;
}

// ---------------- prep_w: MLP=4 (at DRAM floor) ----------------
__global__ void prep_w_kernel(const float* __restrict__ gp, const float* __restrict__ up,
                              const float* __restrict__ dp,
                              bf16* __restrict__ Gh, bf16* __restrict__ Gl,
                              bf16* __restrict__ Uh, bf16* __restrict__ Ul,
                              bf16* __restrict__ Dh, bf16* __restrict__ Dl) {
    const float* src = (blockIdx.y == 0) ? gp : (blockIdx.y == 1) ? up : dp;
    bf16* dh = (blockIdx.y == 0) ? Gh : (blockIdx.y == 1) ? Uh : Dh;
    bf16* dl = (blockIdx.y == 0) ? Gl : (blockIdx.y == 1) ? Ul : Dl;
    size_t blockbase = (size_t)blockIdx.x * 1024;     // in float4 units
    float4 v[4];
#pragma unroll
    for (int i = 0; i < 4; i++)
        v[i] = *(const float4*)(src + (blockbase + i * 256 + threadIdx.x) * 4);
    uint2 ho[4], lo[4];
#pragma unroll
    for (int i = 0; i < 4; i++) split4_packed(v[i], ho[i], lo[i]);
#pragma unroll
    for (int i = 0; i < 4; i++) {
        size_t idx = (blockbase + i * 256 + threadIdx.x) * 4;
        *(uint2*)(dh + idx) = ho[i];
        *(uint2*)(dl + idx) = lo[i];
    }
}

// ---------------- prep_x ----------------
__global__ void prep_x_kernel(const float* __restrict__ hs) {
    int e = blockIdx.y, p = blockIdx.x;
    int count = g_cnt[e];
    size_t row = (size_t)(e * SLOTP + p) * KK;
    if (p >= count) {
        for (int j = threadIdx.x; j < KK / 4; j += 256) {
            *(uint2*)(g_Xh + row + j * 4) = make_uint2(0, 0);
            *(uint2*)(g_Xl + row + j * 4) = make_uint2(0, 0);
        }
        return;
    }
    int t = g_tok[e * CAP + p];
    const float* src = hs + ((size_t)(t & 1) * SS + (size_t)(t >> 1)) * DD;
    for (int j = threadIdx.x; j < KK / 4; j += 256) {
        float4 v = *(const float4*)(src + j * 4);
        uint2 ho, lo;
        split4_packed(v, ho, lo);
        *(uint2*)(g_Xh + row + j * 4) = ho;
        *(uint2*)(g_Xl + row + j * 4) = lo;
    }
}

// ---------------- GEMM geometry: BM=128, separate A/B rings of 3 slots -------
// Term order per k-group: (Ah*Bh), (Al*Bh), (Ah*Bl).
#define ROWB  144
#define TSZ   (128 * ROWB)        // 18432 per slot
#define BOFF  (3 * TSZ)           // B ring at 55296
#define GSMEM (6 * TSZ)           // 110592 -> 2 CTAs/SM

static __device__ __forceinline__ int slotA_of(int k, int j) { return (2 * k + (j == 1 ? 1 : 0)) % 3; }
static __device__ __forceinline__ int slotB_of(int k, int j) { return (2 * k + (j == 2 ? 1 : 0)) % 3; }

// ---------------- ffn1 fused: dual BN=64, SwiGLU epilogue ----------------
__global__ void __launch_bounds__(256, 2)
ffn1_kernel(const bf16* __restrict__ Ah, const bf16* __restrict__ Al,
            const bf16* __restrict__ Gh, const bf16* __restrict__ Gl,
            const bf16* __restrict__ Uh, const bf16* __restrict__ Ul) {
    int e = blockIdx.z;
    int count = g_cnt[e];
    int m0 = blockIdx.y * 128;
    if (m0 >= count) return;
    int n0 = blockIdx.x * 64;

    extern __shared__ char smem[];
    uint32_t sb = smem_u32(smem);
    int tid = threadIdx.x, lane = tid & 31, w = tid >> 5;
    int wm = w >> 1, wn = w & 1;

    const bf16* A_h = Ah + ((size_t)e * SLOTP + m0) * KK;
    const bf16* A_l = Al + ((size_t)e * SLOTP + m0) * KK;
    const bf16* G_h = Gh + (size_t)e * KK * KK + (size_t)n0 * KK;
    const bf16* G_l = Gl + (size_t)e * KK * KK + (size_t)n0 * KK;
    const bf16* U_h = Uh + (size_t)e * KK * KK + (size_t)n0 * KK;
    const bf16* U_l = Ul + (size_t)e * KK * KK + (size_t)n0 * KK;

    uint32_t aBase[2];
#pragma unroll
    for (int mt = 0; mt < 2; mt++)
        aBase[mt] = (uint32_t)((wm * 32 + mt * 16 + (lane & 15)) * ROWB + ((lane >> 4) << 4));
    uint32_t bBase[2][2];
    {
        int grp = lane >> 3, wi = lane & 7;
#pragma unroll
        for (int o = 0; o < 2; o++)
#pragma unroll
            for (int p = 0; p < 2; p++)
                bBase[o][p] = (uint32_t)((o * 64 + wn * 32 + p * 16 + ((grp >> 1) << 3) + wi) * ROWB
                                         + ((grp & 1) << 4));
    }

    float accP[2][4][4], accQ[2][4][4];
#pragma unroll
    for (int i = 0; i < 2; i++)
#pragma unroll
        for (int j = 0; j < 4; j++)
#pragma unroll
            for (int q = 0; q < 4; q++) { accP[i][j][q] = 0.0f; accQ[i][j][q] = 0.0f; }

    auto loadAB = [&](int c) {
        int k = c / 3, j = c - 3 * k;
        int k0 = k << 6;
        if (j != 2) {
            const bf16* As = (j == 1) ? A_l : A_h;
            uint32_t stb = sb + (uint32_t)slotA_of(k, j) * TSZ;
#pragma unroll
            for (int i = 0; i < 4; i++) {
                int id = tid + i * 256;
                int row = id >> 3, sub = id & 7;
                CP16(stb + row * ROWB + sub * 16, As + (size_t)row * KK + k0 + sub * 8);
            }
        }
        if (j != 1) {
            const bf16* Gs = (j == 2) ? G_l : G_h;
            const bf16* Us = (j == 2) ? U_l : U_h;
            uint32_t stb = sb + BOFF + (uint32_t)slotB_of(k, j) * TSZ;
#pragma unroll
            for (int i = 0; i < 4; i++) {
                int id = tid + i * 256;
                int row = id >> 3, sub = id & 7;
                const bf16* src = (row < 64) ? (Gs + (size_t)row * KK) : (Us + (size_t)(row - 64) * KK);
                CP16(stb + row * ROWB + sub * 16, src + k0 + sub * 8);
            }
        }
        CP_COMMIT();
    };

    loadAB(0);

    for (int c = 0; c < NCH2; c++) {
        CP_WAIT0();
        __syncthreads();
        if (c + 1 < NCH2) loadAB(c + 1);
        int k = c / 3, j = c - 3 * k;
        uint32_t baseA = sb + (uint32_t)slotA_of(k, j) * TSZ;
        uint32_t baseB = sb + BOFF + (uint32_t)slotB_of(k, j) * TSZ;
#pragma unroll
        for (int ks = 0; ks < 4; ks++) {
            uint32_t off = (uint32_t)(ks * 32);
            uint32_t a[2][4], bg[2][4], bu[2][4];
            ldsm4(a[0], baseA + aBase[0] + off);
            ldsm4(a[1], baseA + aBase[1] + off);
#pragma unroll
            for (int p = 0; p < 2; p++) { ldsm4(bg[p], baseB + bBase[0][p] + off);
                                          ldsm4(bu[p], baseB + bBase[1][p] + off); }
#pragma unroll
            for (int mt = 0; mt < 2; mt++)
#pragma unroll
                for (int p = 0; p < 2; p++) {
                    mma_bf16(accP[mt][2 * p],     a[mt], bg[p][0], bg[p][1]);
                    mma_bf16(accP[mt][2 * p + 1], a[mt], bg[p][2], bg[p][3]);
                    mma_bf16(accQ[mt][2 * p],     a[mt], bu[p][0], bu[p][1]);
                    mma_bf16(accQ[mt][2 * p + 1], a[mt], bu[p][2], bu[p][3]);
                }
        }
    }

    // epilogue: SwiGLU + split -> Hh/Hl
    size_t rowbase = (size_t)e * SLOTP + m0;
#pragma unroll
    for (int mt = 0; mt < 2; mt++) {
        int row = wm * 32 + mt * 16 + (lane >> 2);
#pragma unroll
        for (int half = 0; half < 2; half++) {
            int rr = row + half * 8;
            bf16* Hhp = g_Hh + (rowbase + rr) * KK + n0;
            bf16* Hlp = g_Hl + (rowbase + rr) * KK + n0;
#pragma unroll
            for (int nt = 0; nt < 4; nt++) {
                int col = wn * 32 + nt * 8 + ((lane & 3) << 1);
                float p0 = accP[mt][nt][2 * half],     q0 = accQ[mt][nt][2 * half];
                float p1 = accP[mt][nt][2 * half + 1], q1 = accQ[mt][nt][2 * half + 1];
                float h0 = silu_f(p0) * q0, h1 = silu_f(p1) * q1;
                uint16_t hh0, ll0, hh1, ll1;
                split2(h0, hh0, ll0); split2(h1, hh1, ll1);
                *(uint32_t*)(Hhp + col) = (uint32_t)hh0 | ((uint32_t)hh1 << 16);
                *(uint32_t*)(Hlp + col) = (uint32_t)ll0 | ((uint32_t)ll1 << 16);
            }
        }
    }
}

// ---------------- ffn2: Y = H dp^T (BM=128, BN=128, 256 thr) ----------------
__global__ void __launch_bounds__(256, 2)
ffn2_kernel(const bf16* __restrict__ Ah, const bf16* __restrict__ Al,
            const bf16* __restrict__ Bh, const bf16* __restrict__ Bl,
            float* __restrict__ C) {
    int e = blockIdx.z;
    int count = g_cnt[e];
    int m0 = blockIdx.y * 128;
    if (m0 >= count) return;
    int n0 = blockIdx.x * 128;

    extern __shared__ char smem[];
    uint32_t sb = smem_u32(smem);
    int tid = threadIdx.x, lane = tid & 31, w = tid >> 5;
    int wm = w >> 1, wn = w & 1;

    const bf16* A_h = Ah + ((size_t)e * SLOTP + m0) * KK;
    const bf16* A_l = Al + ((size_t)e * SLOTP + m0) * KK;
    const bf16* B_h = Bh + (size_t)e * KK * KK + (size_t)n0 * KK;
    const bf16* B_l = Bl + (size_t)e * KK * KK + (size_t)n0 * KK;

    uint32_t aBase[2];
#pragma unroll
    for (int mt = 0; mt < 2; mt++)
        aBase[mt] = (uint32_t)((wm * 32 + mt * 16 + (lane & 15)) * ROWB + ((lane >> 4) << 4));
    uint32_t bBase[4];
    {
        int grp = lane >> 3, wi = lane & 7;
#pragma unroll
        for (int p = 0; p < 4; p++)
            bBase[p] = (uint32_t)((wn * 64 + p * 16 + ((grp >> 1) << 3) + wi) * ROWB + ((grp & 1) << 4));
    }

    float acc[2][8][4];
#pragma unroll
    for (int i = 0; i < 2; i++)
#pragma unroll
        for (int j = 0; j < 8; j++)
#pragma unroll
            for (int q = 0; q < 4; q++) acc[i][j][q] = 0.0f;

    auto loadAB = [&](int c) {
        int k = c / 3, j = c - 3 * k;
        int k0 = k << 6;
        if (j != 2) {
            const bf16* As = (j == 1) ? A_l : A_h;
            uint32_t stb = sb + (uint32_t)slotA_of(k, j) * TSZ;
#pragma unroll
            for (int i = 0; i < 4; i++) {
                int id = tid + i * 256;
                int row = id >> 3, sub = id & 7;
                CP16(stb + row * ROWB + sub * 16, As + (size_t)row * KK + k0 + sub * 8);
            }
        }
        if (j != 1) {
            const bf16* Bs = (j == 2) ? B_l : B_h;
            uint32_t stb = sb + BOFF + (uint32_t)slotB_of(k, j) * TSZ;
#pragma unroll
            for (int i = 0; i < 4; i++) {
                int id = tid + i * 256;
                int row = id >> 3, sub = id & 7;
                CP16(stb + row * ROWB + sub * 16, Bs + (size_t)row * KK + k0 + sub * 8);
            }
        }
        CP_COMMIT();
    };

    loadAB(0);

    for (int c = 0; c < NCH2; c++) {
        CP_WAIT0();
        __syncthreads();
        if (c + 1 < NCH2) loadAB(c + 1);
        int k = c / 3, j = c - 3 * k;
        uint32_t baseA = sb + (uint32_t)slotA_of(k, j) * TSZ;
        uint32_t baseB = sb + BOFF + (uint32_t)slotB_of(k, j) * TSZ;
#pragma unroll
        for (int ks = 0; ks < 4; ks++) {
            uint32_t off = (uint32_t)(ks * 32);
            uint32_t a[2][4], b[4][4];
            ldsm4(a[0], baseA + aBase[0] + off);
            ldsm4(a[1], baseA + aBase[1] + off);
#pragma unroll
            for (int p = 0; p < 4; p++) ldsm4(b[p], baseB + bBase[p] + off);
#pragma unroll
            for (int mt = 0; mt < 2; mt++)
#pragma unroll
                for (int p = 0; p < 4; p++) {
                    mma_bf16(acc[mt][2 * p],     a[mt], b[p][0], b[p][1]);
                    mma_bf16(acc[mt][2 * p + 1], a[mt], b[p][2], b[p][3]);
                }
        }
    }

    float* Cb = C + ((size_t)e * SLOTP + m0) * KK + n0;
#pragma unroll
    for (int mt = 0; mt < 2; mt++) {
        int row = wm * 32 + mt * 16 + (lane >> 2);
#pragma unroll
        for (int nt = 0; nt < 8; nt++) {
            int col = wn * 64 + nt * 8 + ((lane & 3) << 1);
            *(float2*)(Cb + (size_t)row * KK + col)       = make_float2(acc[mt][nt][0], acc[mt][nt][1]);
            *(float2*)(Cb + (size_t)(row + 8) * KK + col) = make_float2(acc[mt][nt][2], acc[mt][nt][3]);
        }
    }
}

// ---------------- combine ----------------
__global__ void combine_kernel(float* __restrict__ out) {
    int n = blockIdx.x;
    int s0 = g_slot[2 * n], s1 = g_slot[2 * n + 1];
    float w0 = g_w[2 * n], w1 = g_w[2 * n + 1];
    int b = n & 1, s = n >> 1;
    float* o = out + (size_t)b * SS * DD + (size_t)s * DD;
    const float* y0 = (s0 >= 0) ? (g_Y + (size_t)s0 * KK) : 0;
    const float* y1 = (s1 >= 0) ? (g_Y + (size_t)s1 * KK) : 0;
    for (int d4 = threadIdx.x; d4 < DD / 4; d4 += 256) {
        float4 v = make_float4(0.f, 0.f, 0.f, 0.f);
        if (y0) {
            float4 a = *(const float4*)(y0 + d4 * 4);
            v.x += w0 * a.x; v.y += w0 * a.y; v.z += w0 * a.z; v.w += w0 * a.w;
        }
        if (y1) {
            float4 a = *(const float4*)(y1 + d4 * 4);
            v.x += w1 * a.x; v.y += w1 * a.y; v.z += w1 * a.z; v.w += w1 * a.w;
        }
        *(float4*)(o + d4 * 4) = v;
    }
}

// ---------------- launch (R13 sequential order) ----------------
extern "C" void kernel_launch(void* const* d_in, const int* in_sizes, int n_in,
                              void* d_out, int out_size) {
    (void)in_sizes; (void)n_in; (void)out_size;
    const float* hs = (const float*)d_in[0];
    const float* wg = (const float*)d_in[1];
    const float* gp = (const float*)d_in[2];
    const float* up = (const float*)d_in[3];
    const float* dp = (const float*)d_in[4];
    float* out = (float*)d_out;

    static int smem_set = 0;
    if (!smem_set) {
        cudaFuncSetAttribute(ffn1_kernel, cudaFuncAttributeMaxDynamicSharedMemorySize, GSMEM);
        cudaFuncSetAttribute(ffn2_kernel, cudaFuncAttributeMaxDynamicSharedMemorySize, GSMEM);
        smem_set = 1;
    }

    bf16 *Gh, *Gl, *Uh, *Ul, *Dh, *Dl, *Xh, *Xl, *Hh, *Hl;
    float *Y;
    cudaGetSymbolAddress((void**)&Gh, g_Gh); cudaGetSymbolAddress((void**)&Gl, g_Gl);
    cudaGetSymbolAddress((void**)&Uh, g_Uh); cudaGetSymbolAddress((void**)&Ul, g_Ul);
    cudaGetSymbolAddress((void**)&Dh, g_Dh); cudaGetSymbolAddress((void**)&Dl, g_Dl);
    cudaGetSymbolAddress((void**)&Xh, g_Xh); cudaGetSymbolAddress((void**)&Xl, g_Xl);
    cudaGetSymbolAddress((void**)&Hh, g_Hh); cudaGetSymbolAddress((void**)&Hl, g_Hl);
    cudaGetSymbolAddress((void**)&Y, g_Y);

    router_kernel<<<NTOK / 2, 128>>>(hs, wg);
    assign_kernel<<<EE, 256>>>();
    prep_x_kernel<<<dim3(SLOTP, EE), 256>>>(hs);
    prep_w_kernel<<<dim3(16384, 3), 256>>>(gp, up, dp, Gh, Gl, Uh, Ul, Dh, Dl);

    ffn1_kernel<<<dim3(KK / 64, SLOTP / 128, EE), 256, GSMEM>>>(Xh, Xl, Gh, Gl, Uh, Ul);
    ffn2_kernel<<<dim3(KK / 128, SLOTP / 128, EE), 256, GSMEM>>>(Hh, Hl, Dh, Dl, Y);
    combine_kernel<<<NTOK, 256>>>(out);
}